// round 8
// baseline (speedup 1.0000x reference)
#include <cuda_runtime.h>
#include <stdint.h>

#define FULLMASK 0xffffffffu

// ---------------- scratch (device globals; referenced ONLY in device code) ----------------
// activations as bf16 (+1/-1), NHWC (stored as raw uint16)
__device__ __align__(16) uint16_t g_X2[128*32*32*128];
__device__ __align__(16) uint16_t g_X3[128*16*16*128];
__device__ __align__(16) uint16_t g_X4[128*16*16*256];
__device__ __align__(16) uint16_t g_X5[128*8*8*256];
__device__ __align__(16) uint16_t g_X6[128*8*8*512];
__device__ __align__(16) float    g_H6[128*4*4*512];
// weights bf16 +-1, layout BT[tap][cout][cin], cin permuted in 16-groups so each
// thread's (b0,b1) mma fragment is one contiguous 8-byte read.
__device__ __align__(16) uint16_t g_B2[9*128*128];
__device__ __align__(16) uint16_t g_B3[9*256*128];
__device__ __align__(16) uint16_t g_B4[9*256*256];
__device__ __align__(16) uint16_t g_B5[9*512*256];
__device__ __align__(16) uint16_t g_B6[9*512*512];

// ---------------- weight sign-packing to bf16 +-1 (fragment-permuted) ----------------
// Within each 16-cin group, word q holds k-pair (q&1)*8 + (q>>1)*2 : thread tig
// reads 8 bytes at tig*8 and gets b0=(k 2t,2t+1), b1=(k 2t+8,2t+9).
__device__ __forceinline__ void pack16(const float* __restrict__ w, uint16_t* __restrict__ bt,
                                       int CIN, int COUT, int o)
{
    int cout = o % COUT;
    int r    = o / COUT;
    int c16  = r % (CIN / 16);
    int tap  = r / (CIN / 16);
    const float* base = w + ((size_t)(tap * CIN + c16 * 16)) * COUT + cout;
    uint32_t wd[8];
    #pragma unroll
    for (int qq = 0; qq < 8; ++qq) {
        int k0 = (qq & 1) * 8 + (qq >> 1) * 2;
        uint32_t lo = (base[(size_t)k0 * COUT]       > 0.f) ? 0x3F80u : 0xBF80u;
        uint32_t hi = (base[(size_t)(k0 + 1) * COUT] > 0.f) ? 0x3F80u : 0xBF80u;
        wd[qq] = lo | (hi << 16);
    }
    uint4* dst = reinterpret_cast<uint4*>(bt + ((size_t)(tap * COUT + cout)) * CIN + c16 * 16);
    dst[0] = make_uint4(wd[0], wd[1], wd[2], wd[3]);
    dst[1] = make_uint4(wd[4], wd[5], wd[6], wd[7]);
}

__global__ void pack_all(const float* __restrict__ w2, const float* __restrict__ w3,
                         const float* __restrict__ w4, const float* __restrict__ w5,
                         const float* __restrict__ w6)
{
    int idx = blockIdx.x * blockDim.x + threadIdx.x;
    if      (idx <   9216) pack16(w2, g_B2, 128, 128, idx);
    else if (idx <  27648) pack16(w3, g_B3, 128, 256, idx - 9216);
    else if (idx <  64512) pack16(w4, g_B4, 256, 256, idx - 27648);
    else if (idx < 138240) pack16(w5, g_B5, 256, 512, idx - 64512);
    else if (idx < 285696) pack16(w6, g_B6, 512, 512, idx - 138240);
}

// ---------------- layer 1: float conv 3->128 + relu + b1 + bn1 -> bf16 sign ----------------
__global__ __launch_bounds__(128) void conv1_kernel(
    const float* __restrict__ x, const float* __restrict__ w1,
    const float* __restrict__ b1, const float* __restrict__ sc1,
    const float* __restrict__ bi1)
{
    __shared__ float xs[3 * 34 * 3];
    const int tid = threadIdx.x;
    const int y = blockIdx.x, b = blockIdx.y;

    for (int i = tid; i < 3 * 34 * 3; i += 128) xs[i] = 0.f;
    __syncthreads();
    for (int j = 0; j < 3; ++j) {
        int gy = y + j - 1;
        if (gy < 0 || gy >= 32) continue;
        if (tid < 96) {
            int c = tid / 3, ci = tid % 3;
            xs[(j * 34 + c + 1) * 3 + ci] = x[((size_t)(b * 32 + gy) * 32 + c) * 3 + ci];
        }
    }
    __syncthreads();

    float wr[27];
    #pragma unroll
    for (int k = 0; k < 27; ++k) wr[k] = w1[k * 128 + tid];
    const float bv = b1[tid], scv = sc1[tid], biv = bi1[tid];

    for (int c = 0; c < 32; ++c) {
        float sum = 0.f;
        #pragma unroll
        for (int ky = 0; ky < 3; ++ky)
            #pragma unroll
            for (int kx = 0; kx < 3; ++kx)
                #pragma unroll
                for (int ci = 0; ci < 3; ++ci)
                    sum += xs[(ky * 34 + c + kx) * 3 + ci] * wr[(ky * 3 + kx) * 3 + ci];
        float h = fmaxf(sum + bv, 0.f);
        float f = __fadd_rn(__fmul_rn(h, scv), biv);
        g_X2[((size_t)(b * 32 + y) * 32 + c) * 128 + tid] = (f > 0.f) ? 0x3F80 : 0xBF80;
    }
}

// ---------------- binary conv as bf16 tensor-core implicit GEMM ----------------
// block 256 thr = 8 warps (2 m x 4 n); tile M=64 pixels, N=128 couts.
// 9-tap shift-accumulated GEMM, K split into KSPLIT staged chunks.
// Buffers selected INSIDE device code via LAYER (device-global symbols are not
// valid as host-passed kernel arguments).
template <int H, int W, int CIN, int COUT, int KSPLIT, bool POOL, bool FOUT, int LAYER>
__global__ __launch_bounds__(256) void binmma(
    const float* __restrict__ scale, const float* __restrict__ bias)
{
    const uint16_t* __restrict__ Xin;
    const uint16_t* __restrict__ BT;
    uint16_t* __restrict__ Xout = nullptr;
    float*    __restrict__ Fout = nullptr;
    if constexpr (LAYER == 2)      { Xin = g_X2; BT = g_B2; Xout = g_X3; }
    else if constexpr (LAYER == 3) { Xin = g_X3; BT = g_B3; Xout = g_X4; }
    else if constexpr (LAYER == 4) { Xin = g_X4; BT = g_B4; Xout = g_X5; }
    else if constexpr (LAYER == 5) { Xin = g_X5; BT = g_B5; Xout = g_X6; }
    else                           { Xin = g_X6; BT = g_B6; Fout = g_H6; }

    constexpr int ROWS  = 64 / W;
    constexpr int SROWS = ROWS + 2;
    constexpr int CINS  = CIN / KSPLIT;
    constexpr int SA_BYTES  = SROWS * W * CINS * 2;
    constexpr int RES_PITCH = 132;
    constexpr int RES_BYTES = 64 * RES_PITCH * 4;
    constexpr int SM_BYTES  = SA_BYTES > RES_BYTES ? SA_BYTES : RES_BYTES;
    __shared__ __align__(16) char smem[SM_BYTES + 32];   // +32B zero pad for ldmatrix
    float* sR = reinterpret_cast<float*>(smem);

    const int tid  = threadIdx.x;
    const int lane = tid & 31, warp = tid >> 5;
    const int wm = warp >> 2, wn = warp & 3;
    const int group = lane >> 2, tig = lane & 3;
    constexpr int TPI = (H * W) / 64;
    const int tile = blockIdx.x;
    const int b  = tile / TPI;
    const int y0 = (tile % TPI) * ROWS;
    const int ny = blockIdx.y;

    const uint32_t s_base = (uint32_t)__cvta_generic_to_shared(smem);
    const uint32_t zaddr  = s_base + SM_BYTES;

    // ldmatrix per-lane row identity: quadrant q (0..3), row rr (0..7)
    const int q  = lane >> 3, rr = lane & 7;
    const int hi16 = (q >> 1) * 16;     // byte offset selecting k8..15 half

    float acc[2][4][4];
    #pragma unroll
    for (int mi = 0; mi < 2; ++mi)
        #pragma unroll
        for (int nf = 0; nf < 4; ++nf)
            #pragma unroll
            for (int v = 0; v < 4; ++v) acc[mi][nf][v] = 0.f;

    for (int ks = 0; ks < KSPLIT; ++ks) {
        if (ks) __syncthreads();
        // ---- stage rows y0-1 .. y0+ROWS of k-chunk ks (zero outside image) ----
        {
            constexpr int CIN8 = CINS / 8;            // uint4 units per pixel chunk
            constexpr int NV = SROWS * W * CIN8;
            const uint4* src = reinterpret_cast<const uint4*>(Xin);
            uint4* dst = reinterpret_cast<uint4*>(smem);
            const size_t imgbase = (size_t)b * H * W * (CIN / 8);
            for (int i = tid; i < NV; i += 256) {
                int c8 = i % CIN8;
                int rest = i / CIN8;
                int xx = rest % W;
                int row = rest / W;
                int gy = y0 - 1 + row;
                uint4 v = make_uint4(0, 0, 0, 0);
                if ((unsigned)gy < (unsigned)H)
                    v = src[imgbase + ((size_t)gy * W + xx) * (CIN / 8) + ks * CIN8 + c8];
                dst[i] = v;
            }
            if (ks == 0 && tid < 8)
                reinterpret_cast<uint32_t*>(smem + SM_BYTES)[tid] = 0u;
        }
        __syncthreads();

        for (int tap = 0; tap < 9; ++tap) {
            const int ky = tap / 3, kx = tap % 3;
            uint32_t abase[2]; bool av2[2];
            #pragma unroll
            for (int mi = 0; mi < 2; ++mi) {
                int p  = wm * 32 + mi * 16 + (q & 1) * 8 + rr;
                int sy = p / W + ky;               // staged row (halo already +1)
                int sx = p % W + kx - 1;
                av2[mi]  = ((unsigned)sx < (unsigned)W);
                abase[mi] = s_base + (uint32_t)((sy * W + sx) * CINS * 2 + hi16);
            }
            const uint2* bv[4];
            #pragma unroll
            for (int nf = 0; nf < 4; ++nf) {
                int n = ny * 128 + wn * 32 + nf * 8 + group;
                bv[nf] = reinterpret_cast<const uint2*>(
                    BT + (size_t)(tap * COUT + n) * CIN + ks * CINS + tig * 4);
            }
            constexpr int KC = CINS / 16;
            #pragma unroll 2
            for (int kc = 0; kc < KC; ++kc) {
                uint32_t A[2][4];
                #pragma unroll
                for (int mi = 0; mi < 2; ++mi) {
                    uint32_t ad = av2[mi] ? (abase[mi] + kc * 32) : zaddr;
                    asm volatile(
                        "ldmatrix.sync.aligned.m8n8.x4.shared.b16 {%0,%1,%2,%3}, [%4];"
                        : "=r"(A[mi][0]), "=r"(A[mi][1]), "=r"(A[mi][2]), "=r"(A[mi][3])
                        : "r"(ad));
                }
                #pragma unroll
                for (int nf = 0; nf < 4; ++nf) {
                    uint2 bw = bv[nf][kc * 4];
                    #pragma unroll
                    for (int mi = 0; mi < 2; ++mi) {
                        asm volatile(
                            "mma.sync.aligned.m16n8k16.row.col.f32.bf16.bf16.f32 "
                            "{%0,%1,%2,%3}, {%4,%5,%6,%7}, {%8,%9}, {%0,%1,%2,%3};"
                            : "+f"(acc[mi][nf][0]), "+f"(acc[mi][nf][1]),
                              "+f"(acc[mi][nf][2]), "+f"(acc[mi][nf][3])
                            : "r"(A[mi][0]), "r"(A[mi][1]), "r"(A[mi][2]), "r"(A[mi][3]),
                              "r"(bw.x), "r"(bw.y));
                    }
                }
            }
        }
    }

    __syncthreads();   // done with sA; reuse smem for results

    // spill accumulators: sR[pixel][n]
    #pragma unroll
    for (int mi = 0; mi < 2; ++mi) {
        int r0 = wm * 32 + mi * 16 + group;
        #pragma unroll
        for (int nf = 0; nf < 4; ++nf) {
            int col = wn * 32 + nf * 8 + tig * 2;
            *reinterpret_cast<float2*>(&sR[r0 * RES_PITCH + col]) =
                make_float2(acc[mi][nf][0], acc[mi][nf][1]);
            *reinterpret_cast<float2*>(&sR[(r0 + 8) * RES_PITCH + col]) =
                make_float2(acc[mi][nf][2], acc[mi][nf][3]);
        }
    }
    __syncthreads();

    // ---- epilogue: relu (+pool) + bn + sign/float store ----
    if constexpr (POOL) {
        int po = tid >> 4;
        int n0 = (tid & 15) * 8;
        int yo_l = po / (W / 2), xo_l = po % (W / 2);
        int p00 = (2 * yo_l) * W + 2 * xo_l;
        float fv[8];
        #pragma unroll
        for (int j = 0; j < 8; ++j) {
            int n = n0 + j;
            float m = fmaxf(fmaxf(sR[p00 * RES_PITCH + n],       sR[(p00 + 1) * RES_PITCH + n]),
                            fmaxf(sR[(p00 + W) * RES_PITCH + n], sR[(p00 + W + 1) * RES_PITCH + n]));
            m = fmaxf(m, 0.f);
            int ng = ny * 128 + n;
            fv[j] = __fadd_rn(__fmul_rn(m, scale[ng]), bias[ng]);
        }
        int yo = y0 / 2 + yo_l;
        size_t obase = (((size_t)b * (H / 2) + yo) * (W / 2) + xo_l) * COUT + ny * 128 + n0;
        if constexpr (FOUT) {
            #pragma unroll
            for (int j = 0; j < 8; ++j) Fout[obase + j] = fv[j];
        } else {
            uint32_t wds[4];
            #pragma unroll
            for (int qq = 0; qq < 4; ++qq) {
                uint32_t lo = (fv[2 * qq]     > 0.f) ? 0x3F80u : 0xBF80u;
                uint32_t hi = (fv[2 * qq + 1] > 0.f) ? 0x3F80u : 0xBF80u;
                wds[qq] = lo | (hi << 16);
            }
            *reinterpret_cast<uint4*>(Xout + obase) = make_uint4(wds[0], wds[1], wds[2], wds[3]);
        }
    } else {
        int pix = tid >> 2;
        int n0 = (tid & 3) * 32;
        int y = y0 + pix / W, xx = pix % W;
        size_t obase = (((size_t)b * H + y) * W + xx) * COUT + ny * 128 + n0;
        uint32_t wds[16];
        #pragma unroll
        for (int qq = 0; qq < 16; ++qq) {
            int n = n0 + 2 * qq;
            float v0 = fmaxf(sR[pix * RES_PITCH + n], 0.f);
            float v1 = fmaxf(sR[pix * RES_PITCH + n + 1], 0.f);
            float f0 = __fadd_rn(__fmul_rn(v0, scale[ny * 128 + n]),     bias[ny * 128 + n]);
            float f1 = __fadd_rn(__fmul_rn(v1, scale[ny * 128 + n + 1]), bias[ny * 128 + n + 1]);
            wds[qq] = ((f0 > 0.f) ? 0x3F80u : 0xBF80u) | (((f1 > 0.f) ? 0x3F80u : 0xBF80u) << 16);
        }
        uint4* op = reinterpret_cast<uint4*>(Xout + obase);
        op[0] = make_uint4(wds[0],  wds[1],  wds[2],  wds[3]);
        op[1] = make_uint4(wds[4],  wds[5],  wds[6],  wds[7]);
        op[2] = make_uint4(wds[8],  wds[9],  wds[10], wds[11]);
        op[3] = make_uint4(wds[12], wds[13], wds[14], wds[15]);
    }
}

// ---------------- dense (512->10) + softmax, one warp per pixel ----------------
__global__ __launch_bounds__(128) void dense_kernel(
    const float* __restrict__ dw, const float* __restrict__ db, float* __restrict__ out)
{
    __shared__ float sdw[512 * 10];
    const int tid = threadIdx.x;
    for (int i = tid; i < 5120; i += 128) {
        int c = i / 10, d = i % 10;
        sdw[d * 512 + c] = dw[i];
    }
    __syncthreads();
    const int warp = tid >> 5, lane = tid & 31;
    const int p = blockIdx.x * 4 + warp;
    float lg[10];
    #pragma unroll
    for (int d = 0; d < 10; ++d) lg[d] = 0.f;
    for (int c = lane; c < 512; c += 32) {
        float h = g_H6[(size_t)p * 512 + c];
        #pragma unroll
        for (int d = 0; d < 10; ++d) lg[d] += h * sdw[d * 512 + c];
    }
    #pragma unroll
    for (int d = 0; d < 10; ++d)
        for (int off = 16; off; off >>= 1)
            lg[d] += __shfl_xor_sync(FULLMASK, lg[d], off);
    if (lane == 0) {
        float l[10], mx = -1e30f;
        #pragma unroll
        for (int d = 0; d < 10; ++d) { l[d] = lg[d] + db[d]; mx = fmaxf(mx, l[d]); }
        float e[10], ssum = 0.f;
        #pragma unroll
        for (int d = 0; d < 10; ++d) { e[d] = expf(l[d] - mx); ssum += e[d]; }
        float inv = 1.f / ssum;
        #pragma unroll
        for (int d = 0; d < 10; ++d) out[(size_t)p * 10 + d] = e[d] * inv;
    }
}

// ---------------- launch ----------------
extern "C" void kernel_launch(void* const* d_in, const int* in_sizes, int n_in,
                              void* d_out, int out_size)
{
    const float* P[22];
    for (int i = 0; i < 22 && i < n_in; ++i) P[i] = (const float*)d_in[i];

    const float *x, *w1, *b1, *w2, *w3, *w4, *w5, *w6;
    const float *bn1s, *bn1b, *bn2s, *bn2b, *bn3s, *bn3b, *bn4s, *bn4b, *bn5s, *bn5b, *bn6s, *bn6b;
    const float *dw, *db;

    if (in_sizes[3] == 147456) {
        // setup_inputs dict order
        x = P[0];  w1 = P[1]; b1 = P[2];
        w2 = P[3]; w3 = P[4]; w4 = P[5]; w5 = P[6]; w6 = P[7];
        bn1s = P[8];  bn1b = P[9];  bn2s = P[10]; bn2b = P[11];
        bn3s = P[12]; bn3b = P[13]; bn4s = P[14]; bn4b = P[15];
        bn5s = P[16]; bn5b = P[17]; bn6s = P[18]; bn6b = P[19];
        dw = P[20]; db = P[21];
    } else {
        // reference() signature order
        x = P[0];  w1 = P[1]; b1 = P[2]; bn1s = P[3]; bn1b = P[4];
        w2 = P[5];  bn2s = P[6];  bn2b = P[7];
        w3 = P[8];  bn3s = P[9];  bn3b = P[10];
        w4 = P[11]; bn4s = P[12]; bn4b = P[13];
        w5 = P[14]; bn5s = P[15]; bn5b = P[16];
        w6 = P[17]; bn6s = P[18]; bn6b = P[19];
        dw = P[20]; db = P[21];
    }

    pack_all<<<(285696 + 255) / 256, 256>>>(w2, w3, w4, w5, w6);

    conv1_kernel<<<dim3(32, 128), 128>>>(x, w1, b1, bn1s, bn1b);

    binmma<32, 32, 128, 128, 1, true,  false, 2><<<dim3(2048, 1), 256>>>(bn2s, bn2b);
    binmma<16, 16, 128, 256, 1, false, false, 3><<<dim3(512, 2),  256>>>(bn3s, bn3b);
    binmma<16, 16, 256, 256, 2, true,  false, 4><<<dim3(512, 2),  256>>>(bn4s, bn4b);
    binmma<8,  8,  256, 512, 1, false, false, 5><<<dim3(128, 4),  256>>>(bn5s, bn5b);
    binmma<8,  8,  512, 512, 2, true,  true,  6><<<dim3(128, 4),  256>>>(bn6s, bn6b);

    dense_kernel<<<512, 128>>>(dw, db, (float*)d_out);
}

// round 10
// speedup vs baseline: 1.5956x; 1.5956x over previous
#include <cuda_runtime.h>
#include <stdint.h>

#define FULLMASK 0xffffffffu

// ---------------- scratch (device globals; referenced ONLY in device code) ----------------
// activations int8 (+1/-1), NHWC
__device__ __align__(256) int8_t g_X2[128*32*32*128];
__device__ __align__(256) int8_t g_X3[128*16*16*128];
__device__ __align__(256) int8_t g_X4[128*16*16*256];
__device__ __align__(256) int8_t g_X5[128*8*8*256];
__device__ __align__(256) int8_t g_X6[128*8*8*512];
__device__ __align__(256) float  g_H6[128*4*4*512];
// weights s8 +-1, layout [tap][cout][cin], each 32B k-chunk byte-permuted so one
// LDG.64 per lane yields the IMMA B fragment (b0 = k tig*4.., b1 = k 16+tig*4..).
__device__ __align__(256) int8_t g_B2[9*128*128];
__device__ __align__(256) int8_t g_B3[9*256*128];
__device__ __align__(256) int8_t g_B4[9*256*256];
__device__ __align__(256) int8_t g_B5[9*512*256];
__device__ __align__(256) int8_t g_B6[9*512*512];

// ---------------- weight sign-packing (fragment-permuted s8) ----------------
__device__ __forceinline__ void pack32(const float* __restrict__ w, int8_t* __restrict__ bt,
                                       int CIN, int COUT, int o)
{
    int cout = o % COUT;
    int r    = o / COUT;
    int KCL  = CIN / 32;
    int kc   = r % KCL;
    int tap  = r / KCL;
    const float* base = w + ((size_t)(tap * CIN + kc * 32)) * COUT + cout;
    uint32_t wd[8];
    #pragma unroll
    for (int q = 0; q < 8; ++q) {
        uint32_t v = 0;
        #pragma unroll
        for (int j = 0; j < 4; ++j) {
            int p = q * 4 + j;              // byte position 0..31
            int t = p >> 3, u = p & 7;
            int k0 = (u < 4) ? (t * 4 + u) : (12 + t * 4 + u);   // 16 + t*4 + (u-4)
            uint32_t bb = (base[(size_t)k0 * COUT] > 0.f) ? 0x01u : 0xFFu;
            v |= bb << (8 * j);
        }
        wd[q] = v;
    }
    uint4* dst = reinterpret_cast<uint4*>(bt + ((size_t)(tap * COUT + cout)) * CIN + kc * 32);
    dst[0] = make_uint4(wd[0], wd[1], wd[2], wd[3]);
    dst[1] = make_uint4(wd[4], wd[5], wd[6], wd[7]);
}

__global__ void pack_all(const float* __restrict__ w2, const float* __restrict__ w3,
                         const float* __restrict__ w4, const float* __restrict__ w5,
                         const float* __restrict__ w6)
{
    int idx = blockIdx.x * blockDim.x + threadIdx.x;
    if      (idx <   4608) pack32(w2, g_B2, 128, 128, idx);
    else if (idx <  13824) pack32(w3, g_B3, 128, 256, idx - 4608);
    else if (idx <  32256) pack32(w4, g_B4, 256, 256, idx - 13824);
    else if (idx <  69120) pack32(w5, g_B5, 256, 512, idx - 32256);
    else if (idx < 142848) pack32(w6, g_B6, 512, 512, idx - 69120);
}

// ---------------- layer 1: float conv 3->128 + relu + b1 + bn1 -> s8 sign ----------------
__global__ __launch_bounds__(128) void conv1_kernel(
    const float* __restrict__ x, const float* __restrict__ w1,
    const float* __restrict__ b1, const float* __restrict__ sc1,
    const float* __restrict__ bi1)
{
    __shared__ float xs[3 * 34 * 3];
    const int tid = threadIdx.x;
    const int y = blockIdx.x, b = blockIdx.y;

    for (int i = tid; i < 3 * 34 * 3; i += 128) xs[i] = 0.f;
    __syncthreads();
    for (int j = 0; j < 3; ++j) {
        int gy = y + j - 1;
        if (gy < 0 || gy >= 32) continue;
        if (tid < 96) {
            int c = tid / 3, ci = tid % 3;
            xs[(j * 34 + c + 1) * 3 + ci] = x[((size_t)(b * 32 + gy) * 32 + c) * 3 + ci];
        }
    }
    __syncthreads();

    float wr[27];
    #pragma unroll
    for (int k = 0; k < 27; ++k) wr[k] = w1[k * 128 + tid];
    const float bv = b1[tid], scv = sc1[tid], biv = bi1[tid];

    for (int c = 0; c < 32; ++c) {
        float sum = 0.f;
        #pragma unroll
        for (int ky = 0; ky < 3; ++ky)
            #pragma unroll
            for (int kx = 0; kx < 3; ++kx)
                #pragma unroll
                for (int ci = 0; ci < 3; ++ci)
                    sum += xs[(ky * 34 + c + kx) * 3 + ci] * wr[(ky * 3 + kx) * 3 + ci];
        float h = fmaxf(sum + bv, 0.f);
        float f = __fadd_rn(__fmul_rn(h, scv), biv);
        g_X2[((size_t)(b * 32 + y) * 32 + c) * 128 + tid] = (f > 0.f) ? (int8_t)1 : (int8_t)-1;
    }
}

// ---------------- layer params ----------------
template <int L> struct LP;
template <> struct LP<2> { static constexpr int H=32,W=32,CIN=128,COUT=128,WM=4,WN=2; static constexpr bool POOL=true,  FOUT=false; };
template <> struct LP<3> { static constexpr int H=16,W=16,CIN=128,COUT=256,WM=2,WN=4; static constexpr bool POOL=false, FOUT=false; };
template <> struct LP<4> { static constexpr int H=16,W=16,CIN=256,COUT=256,WM=2,WN=4; static constexpr bool POOL=true,  FOUT=false; };
template <> struct LP<5> { static constexpr int H=8, W=8, CIN=256,COUT=512,WM=2,WN=4; static constexpr bool POOL=false, FOUT=false; };
template <> struct LP<6> { static constexpr int H=8, W=8, CIN=512,COUT=512,WM=2,WN=4; static constexpr bool POOL=true,  FOUT=true;  };

// ---------------- binary conv: s8 IMMA implicit GEMM, swizzled smem ----------------
// block 256 thr = 8 warps (WM x WN); warp tile m32 x n64 (2 mi x 8 nf), k32 IMMA.
template <int L>
__global__ __launch_bounds__(256) void tcconv(const float* __restrict__ scale,
                                              const float* __restrict__ bias)
{
    constexpr int H = LP<L>::H, W = LP<L>::W, CIN = LP<L>::CIN, COUT = LP<L>::COUT;
    constexpr int WM = LP<L>::WM, WN = LP<L>::WN;
    constexpr bool POOL = LP<L>::POOL, FOUT = LP<L>::FOUT;
    constexpr int M = WM * 32, NB = WN * 64;
    constexpr int MROWS = M / W;
    constexpr int TPI = H / MROWS;
    constexpr int CPP = CIN / 16;            // 16B units per pixel
    constexpr int KC = CIN / 32;
    constexpr int SROWS = MROWS + 2;
    constexpr int A_BYTES = SROWS * W * CIN;
    constexpr int RES_BYTES = 64 * 132 * 4;
    constexpr int SM_BYTES = (A_BYTES > RES_BYTES ? A_BYTES : RES_BYTES);

    const int8_t* __restrict__ Xin;
    const int8_t* __restrict__ BT;
    int8_t* __restrict__ Xout = nullptr;
    float*  __restrict__ Fout = nullptr;
    if constexpr (L == 2)      { Xin = g_X2; BT = g_B2; Xout = g_X3; }
    else if constexpr (L == 3) { Xin = g_X3; BT = g_B3; Xout = g_X4; }
    else if constexpr (L == 4) { Xin = g_X4; BT = g_B4; Xout = g_X5; }
    else if constexpr (L == 5) { Xin = g_X5; BT = g_B5; Xout = g_X6; }
    else                       { Xin = g_X6; BT = g_B6; Fout = g_H6; }

    __shared__ __align__(16) uint8_t smem[SM_BYTES + 16];
    int* sR = reinterpret_cast<int*>(smem);

    const int tid  = threadIdx.x;
    const int lane = tid & 31, warp = tid >> 5;
    const int wm = warp / WN, wn = warp % WN;
    const int group = lane >> 2, tig = lane & 3;
    const int q = lane >> 3, rr = lane & 7;
    const int h = q >> 1;                    // k-half this lane feeds

    const int bx = blockIdx.x, ny = blockIdx.y;
    const int b = bx / TPI, tile = bx % TPI;
    const int iy0 = tile * MROWS;
    const int nybase = ny * NB;

    const uint32_t sbase = (uint32_t)__cvta_generic_to_shared(smem);
    const uint32_t zaddr = sbase + SM_BYTES;
    if (tid < 4) *reinterpret_cast<uint32_t*>(smem + SM_BYTES + tid * 4) = 0u;

    // ---- stage A rows iy0-1 .. iy0+MROWS, swizzled (chunk16 ^= pixel&7) ----
    {
        constexpr int NV = SROWS * W * CPP;
        for (int i = tid; i < NV; i += 256) {
            int sp = i / CPP, c16 = i - sp * CPP;
            int gy = iy0 - 1 + sp / W, gx = sp % W;
            uint4 v = make_uint4(0, 0, 0, 0);
            if ((unsigned)gy < (unsigned)H)
                v = *reinterpret_cast<const uint4*>(
                    Xin + (((size_t)b * H + gy) * W + gx) * CIN + c16 * 16);
            int d16 = sp * CPP + (c16 ^ (sp & 7));
            *reinterpret_cast<uint4*>(smem + d16 * 16) = v;
        }
    }
    __syncthreads();

    // per-nf byte offset into a tap slab of BT
    size_t noff[8];
    #pragma unroll
    for (int nf = 0; nf < 8; ++nf)
        noff[nf] = (size_t)(nybase + wn * 64 + nf * 8 + group) * CIN + tig * 4 * 2;

    int acc[2][8][4];
    #pragma unroll
    for (int mi = 0; mi < 2; ++mi)
        #pragma unroll
        for (int nf = 0; nf < 8; ++nf)
            #pragma unroll
            for (int v = 0; v < 4; ++v) acc[mi][nf][v] = 0;

    for (int tap = 0; tap < 9; ++tap) {
        const int ky = tap / 3, kx = tap % 3;
        uint32_t abase[2], ax7[2]; bool av[2];
        #pragma unroll
        for (int mi = 0; mi < 2; ++mi) {
            int p  = wm * 32 + mi * 16 + (q & 1) * 8 + rr;   // this lane's A row (pixel)
            int ry = p / W, px = p - ry * W;
            int sx = px + kx - 1;
            av[mi] = ((unsigned)sx < (unsigned)W);           // row halo staged as zeros
            int sp = (ry + ky) * W + sx;
            abase[mi] = sbase + (uint32_t)(sp * CPP * 16);
            ax7[mi]   = (uint32_t)(sp & 7);
        }
        const int8_t* btap = BT + (size_t)tap * COUT * CIN;
        #pragma unroll 2
        for (int kc = 0; kc < KC; ++kc) {
            uint32_t A[2][4];
            #pragma unroll
            for (int mi = 0; mi < 2; ++mi) {
                uint32_t c16v = ((uint32_t)(kc * 2 + h)) ^ ax7[mi];
                uint32_t ad = av[mi] ? (abase[mi] + (c16v << 4)) : zaddr;
                asm volatile(
                    "ldmatrix.sync.aligned.m8n8.x4.shared.b16 {%0,%1,%2,%3}, [%4];"
                    : "=r"(A[mi][0]), "=r"(A[mi][1]), "=r"(A[mi][2]), "=r"(A[mi][3])
                    : "r"(ad));
            }
            #pragma unroll
            for (int nf = 0; nf < 8; ++nf) {
                uint2 bw = *reinterpret_cast<const uint2*>(btap + noff[nf] + kc * 32);
                #pragma unroll
                for (int mi = 0; mi < 2; ++mi) {
                    asm volatile(
                        "mma.sync.aligned.m16n8k32.row.col.s32.s8.s8.s32 "
                        "{%0,%1,%2,%3}, {%4,%5,%6,%7}, {%8,%9}, {%0,%1,%2,%3};"
                        : "+r"(acc[mi][nf][0]), "+r"(acc[mi][nf][1]),
                          "+r"(acc[mi][nf][2]), "+r"(acc[mi][nf][3])
                        : "r"(A[mi][0]), "r"(A[mi][1]), "r"(A[mi][2]), "r"(A[mi][3]),
                          "r"(bw.x), "r"(bw.y));
                }
            }
        }
    }
    __syncthreads();   // smem A no longer needed; reuse as result buffer

    // ---- epilogue in 2 rounds of 64 rows x 128 cols ----
    constexpr bool MH_SPLIT = (M > 64);
    #pragma unroll
    for (int rd = 0; rd < 2; ++rd) {
        const int mh = MH_SPLIT ? rd : 0;
        const int nh = MH_SPLIT ? 0 : rd;
        const bool mine = MH_SPLIT ? ((wm >> 1) == mh) : ((wn >> 1) == nh);
        if (mine) {
            const int rowbase = MH_SPLIT ? (wm & 1) * 32 : wm * 32;
            const int colbase = MH_SPLIT ? wn * 64 : (wn & 1) * 64;
            #pragma unroll
            for (int mi = 0; mi < 2; ++mi) {
                int r0 = rowbase + mi * 16 + group;
                #pragma unroll
                for (int nf = 0; nf < 8; ++nf) {
                    int col = colbase + nf * 8 + tig * 2;
                    *reinterpret_cast<int2*>(&sR[r0 * 132 + col]) =
                        make_int2(acc[mi][nf][0], acc[mi][nf][1]);
                    *reinterpret_cast<int2*>(&sR[(r0 + 8) * 132 + col]) =
                        make_int2(acc[mi][nf][2], acc[mi][nf][3]);
                }
            }
        }
        __syncthreads();

        if constexpr (POOL) {
            // 16 out px x 128 n per round; 16 threads/px, 8 n each
            int po = tid >> 4;
            int n0 = (tid & 15) * 8;
            int yo_l = po / (W / 2), xo_l = po % (W / 2);
            int p00 = (2 * yo_l) * W + 2 * xo_l;
            float fv[8];
            #pragma unroll
            for (int j = 0; j < 8; ++j) {
                int n = n0 + j;
                int m01 = max(sR[p00 * 132 + n],       sR[(p00 + 1) * 132 + n]);
                int m23 = max(sR[(p00 + W) * 132 + n], sR[(p00 + W + 1) * 132 + n]);
                int v = max(max(m01, m23), 0);
                int ng = nybase + nh * 128 + n;
                fv[j] = __fadd_rn(__fmul_rn((float)v, scale[ng]), bias[ng]);
            }
            int yo = iy0 / 2 + mh * ((64 / W) / 2) + yo_l;
            int xo = xo_l;
            size_t obase = (((size_t)b * (H / 2) + yo) * (W / 2) + xo) * COUT
                           + nybase + nh * 128 + n0;
            if constexpr (FOUT) {
                float* op = Fout + obase;
                *reinterpret_cast<float4*>(op)     = make_float4(fv[0], fv[1], fv[2], fv[3]);
                *reinterpret_cast<float4*>(op + 4) = make_float4(fv[4], fv[5], fv[6], fv[7]);
            } else {
                uint32_t w0 = 0, w1 = 0;
                #pragma unroll
                for (int j = 0; j < 4; ++j) {
                    w0 |= ((fv[j]     > 0.f) ? 0x01u : 0xFFu) << (8 * j);
                    w1 |= ((fv[4 + j] > 0.f) ? 0x01u : 0xFFu) << (8 * j);
                }
                *reinterpret_cast<uint2*>(Xout + obase) = make_uint2(w0, w1);
            }
        } else {
            // 64 px x 128 n per round; 4 iterations of 256 thr x 8 n
            #pragma unroll
            for (int it = 0; it < 4; ++it) {
                int t = it * 256 + tid;
                int lp = t >> 4;
                int n0 = (t & 15) * 8;
                int y = iy0 + lp / W, x = lp % W;
                uint32_t w0 = 0, w1 = 0;
                #pragma unroll
                for (int j = 0; j < 8; ++j) {
                    int n = n0 + j;
                    int v = max(sR[lp * 132 + n], 0);
                    int ng = nybase + nh * 128 + n;
                    float f = __fadd_rn(__fmul_rn((float)v, scale[ng]), bias[ng]);
                    uint32_t bb = (f > 0.f) ? 0x01u : 0xFFu;
                    if (j < 4) w0 |= bb << (8 * j);
                    else       w1 |= bb << (8 * (j - 4));
                }
                size_t obase = (((size_t)b * H + y) * W + x) * COUT + nybase + nh * 128 + n0;
                *reinterpret_cast<uint2*>(Xout + obase) = make_uint2(w0, w1);
            }
        }
        __syncthreads();
    }
}

// ---------------- dense (512->10) + softmax, one warp per pixel ----------------
__global__ __launch_bounds__(128) void dense_kernel(
    const float* __restrict__ dw, const float* __restrict__ db, float* __restrict__ out)
{
    __shared__ float sdw[512 * 10];
    const int tid = threadIdx.x;
    for (int i = tid; i < 5120; i += 128) {
        int c = i / 10, d = i % 10;
        sdw[d * 512 + c] = dw[i];
    }
    __syncthreads();
    const int warp = tid >> 5, lane = tid & 31;
    const int p = blockIdx.x * 4 + warp;
    float lg[10];
    #pragma unroll
    for (int d = 0; d < 10; ++d) lg[d] = 0.f;
    for (int c = lane; c < 512; c += 32) {
        float hh = g_H6[(size_t)p * 512 + c];
        #pragma unroll
        for (int d = 0; d < 10; ++d) lg[d] += hh * sdw[d * 512 + c];
    }
    #pragma unroll
    for (int d = 0; d < 10; ++d)
        for (int off = 16; off; off >>= 1)
            lg[d] += __shfl_xor_sync(FULLMASK, lg[d], off);
    if (lane == 0) {
        float l[10], mx = -1e30f;
        #pragma unroll
        for (int d = 0; d < 10; ++d) { l[d] = lg[d] + db[d]; mx = fmaxf(mx, l[d]); }
        float e[10], ssum = 0.f;
        #pragma unroll
        for (int d = 0; d < 10; ++d) { e[d] = expf(l[d] - mx); ssum += e[d]; }
        float inv = 1.f / ssum;
        #pragma unroll
        for (int d = 0; d < 10; ++d) out[(size_t)p * 10 + d] = e[d] * inv;
    }
}

// ---------------- launch ----------------
extern "C" void kernel_launch(void* const* d_in, const int* in_sizes, int n_in,
                              void* d_out, int out_size)
{
    const float* P[22];
    for (int i = 0; i < 22 && i < n_in; ++i) P[i] = (const float*)d_in[i];

    const float *x, *w1, *b1, *w2, *w3, *w4, *w5, *w6;
    const float *bn1s, *bn1b, *bn2s, *bn2b, *bn3s, *bn3b, *bn4s, *bn4b, *bn5s, *bn5b, *bn6s, *bn6b;
    const float *dw, *db;

    if (in_sizes[3] == 147456) {
        // setup_inputs dict order
        x = P[0];  w1 = P[1]; b1 = P[2];
        w2 = P[3]; w3 = P[4]; w4 = P[5]; w5 = P[6]; w6 = P[7];
        bn1s = P[8];  bn1b = P[9];  bn2s = P[10]; bn2b = P[11];
        bn3s = P[12]; bn3b = P[13]; bn4s = P[14]; bn4b = P[15];
        bn5s = P[16]; bn5b = P[17]; bn6s = P[18]; bn6b = P[19];
        dw = P[20]; db = P[21];
    } else {
        // reference() signature order
        x = P[0];  w1 = P[1]; b1 = P[2]; bn1s = P[3]; bn1b = P[4];
        w2 = P[5];  bn2s = P[6];  bn2b = P[7];
        w3 = P[8];  bn3s = P[9];  bn3b = P[10];
        w4 = P[11]; bn4s = P[12]; bn4b = P[13];
        w5 = P[14]; bn5s = P[15]; bn5b = P[16];
        w6 = P[17]; bn6s = P[18]; bn6b = P[19];
        dw = P[20]; db = P[21];
    }

    pack_all<<<(142848 + 255) / 256, 256>>>(w2, w3, w4, w5, w6);

    conv1_kernel<<<dim3(32, 128), 128>>>(x, w1, b1, bn1s, bn1b);

    tcconv<2><<<dim3(128 * 8, 1), 256>>>(bn2s, bn2b);
    tcconv<3><<<dim3(128 * 4, 1), 256>>>(bn3s, bn3b);
    tcconv<4><<<dim3(128 * 4, 1), 256>>>(bn4s, bn4b);
    tcconv<5><<<dim3(128, 2),    256>>>(bn5s, bn5b);
    tcconv<6><<<dim3(128, 2),    256>>>(bn6s, bn6b);

    dense_kernel<<<512, 128>>>(dw, db, (float*)d_out);
}

// round 11
// speedup vs baseline: 2.0429x; 1.2803x over previous
#include <cuda_runtime.h>
#include <stdint.h>

#define FULLMASK 0xffffffffu

// ---------------- scratch (device globals; referenced ONLY in device code) ----------------
// activations bf16 (+1/-1) raw uint16, NHWC
__device__ __align__(256) uint16_t g_X2[128*32*32*128];
__device__ __align__(256) uint16_t g_X3[128*16*16*128];
__device__ __align__(256) uint16_t g_X4[128*16*16*256];
__device__ __align__(256) uint16_t g_X5[128*8*8*256];
__device__ __align__(256) uint16_t g_X6[128*8*8*512];
__device__ __align__(256) float    g_H6[128*4*4*512];
// weights bf16 +-1, layout [tap][cout][cin], cin permuted in 16-groups so each
// thread's (b0,b1) mma fragment is one contiguous 8-byte read (validated R8).
__device__ __align__(256) uint16_t g_B2[9*128*128];
__device__ __align__(256) uint16_t g_B3[9*256*128];
__device__ __align__(256) uint16_t g_B4[9*256*256];
__device__ __align__(256) uint16_t g_B5[9*512*256];
__device__ __align__(256) uint16_t g_B6[9*512*512];

// ---------------- weight sign-packing to bf16 +-1 (fragment-permuted) ----------------
__device__ __forceinline__ void pack16(const float* __restrict__ w, uint16_t* __restrict__ bt,
                                       int CIN, int COUT, int o)
{
    int cout = o % COUT;
    int r    = o / COUT;
    int c16  = r % (CIN / 16);
    int tap  = r / (CIN / 16);
    const float* base = w + ((size_t)(tap * CIN + c16 * 16)) * COUT + cout;
    uint32_t wd[8];
    #pragma unroll
    for (int qq = 0; qq < 8; ++qq) {
        int k0 = (qq & 1) * 8 + (qq >> 1) * 2;
        uint32_t lo = (base[(size_t)k0 * COUT]       > 0.f) ? 0x3F80u : 0xBF80u;
        uint32_t hi = (base[(size_t)(k0 + 1) * COUT] > 0.f) ? 0x3F80u : 0xBF80u;
        wd[qq] = lo | (hi << 16);
    }
    uint4* dst = reinterpret_cast<uint4*>(bt + ((size_t)(tap * COUT + cout)) * CIN + c16 * 16);
    dst[0] = make_uint4(wd[0], wd[1], wd[2], wd[3]);
    dst[1] = make_uint4(wd[4], wd[5], wd[6], wd[7]);
}

__global__ void pack_all(const float* __restrict__ w2, const float* __restrict__ w3,
                         const float* __restrict__ w4, const float* __restrict__ w5,
                         const float* __restrict__ w6)
{
    int idx = blockIdx.x * blockDim.x + threadIdx.x;
    if      (idx <   9216) pack16(w2, g_B2, 128, 128, idx);
    else if (idx <  27648) pack16(w3, g_B3, 128, 256, idx - 9216);
    else if (idx <  64512) pack16(w4, g_B4, 256, 256, idx - 27648);
    else if (idx < 138240) pack16(w5, g_B5, 256, 512, idx - 64512);
    else if (idx < 285696) pack16(w6, g_B6, 512, 512, idx - 138240);
}

// ---------------- layer 1: float conv 3->128 + relu + b1 + bn1 -> bf16 sign ----------------
__global__ __launch_bounds__(128) void conv1_kernel(
    const float* __restrict__ x, const float* __restrict__ w1,
    const float* __restrict__ b1, const float* __restrict__ sc1,
    const float* __restrict__ bi1)
{
    __shared__ float xs[3 * 34 * 3];
    const int tid = threadIdx.x;
    const int y = blockIdx.x, b = blockIdx.y;

    for (int i = tid; i < 3 * 34 * 3; i += 128) xs[i] = 0.f;
    __syncthreads();
    for (int j = 0; j < 3; ++j) {
        int gy = y + j - 1;
        if (gy < 0 || gy >= 32) continue;
        if (tid < 96) {
            int c = tid / 3, ci = tid % 3;
            xs[(j * 34 + c + 1) * 3 + ci] = x[((size_t)(b * 32 + gy) * 32 + c) * 3 + ci];
        }
    }
    __syncthreads();

    float wr[27];
    #pragma unroll
    for (int k = 0; k < 27; ++k) wr[k] = w1[k * 128 + tid];
    const float bv = b1[tid], scv = sc1[tid], biv = bi1[tid];

    for (int c = 0; c < 32; ++c) {
        float sum = 0.f;
        #pragma unroll
        for (int ky = 0; ky < 3; ++ky)
            #pragma unroll
            for (int kx = 0; kx < 3; ++kx)
                #pragma unroll
                for (int ci = 0; ci < 3; ++ci)
                    sum += xs[(ky * 34 + c + kx) * 3 + ci] * wr[(ky * 3 + kx) * 3 + ci];
        float h = fmaxf(sum + bv, 0.f);
        float f = __fadd_rn(__fmul_rn(h, scv), biv);
        g_X2[((size_t)(b * 32 + y) * 32 + c) * 128 + tid] = (f > 0.f) ? 0x3F80 : 0xBF80;
    }
}

// ---------------- layer params (tile M=64 x N=128 everywhere) ----------------
template <int L> struct LP;
template <> struct LP<2> { static constexpr int H=32,W=32,CIN=128,COUT=128,KSPLIT=1; static constexpr bool POOL=true,  FOUT=false; };
template <> struct LP<3> { static constexpr int H=16,W=16,CIN=128,COUT=256,KSPLIT=1; static constexpr bool POOL=false, FOUT=false; };
template <> struct LP<4> { static constexpr int H=16,W=16,CIN=256,COUT=256,KSPLIT=2; static constexpr bool POOL=true,  FOUT=false; };
template <> struct LP<5> { static constexpr int H=8, W=8, CIN=256,COUT=512,KSPLIT=1; static constexpr bool POOL=false, FOUT=false; };
template <> struct LP<6> { static constexpr int H=8, W=8, CIN=512,COUT=512,KSPLIT=2; static constexpr bool POOL=true,  FOUT=true;  };

// ---------------- binary conv: bf16 HMMA implicit GEMM, swizzled smem ----------------
// block 256 thr = 8 warps (2 m x 4 n); warp tile m32 x n32; k16 bf16 mma.
template <int L>
__global__ __launch_bounds__(256) void tcconv(const float* __restrict__ scale,
                                              const float* __restrict__ bias)
{
    constexpr int H = LP<L>::H, W = LP<L>::W, CIN = LP<L>::CIN, COUT = LP<L>::COUT;
    constexpr int KSPLIT = LP<L>::KSPLIT;
    constexpr bool POOL = LP<L>::POOL, FOUT = LP<L>::FOUT;
    constexpr int MROWS = 64 / W;
    constexpr int TPI = H / MROWS;
    constexpr int SROWS = MROWS + 2;
    constexpr int CINS = CIN / KSPLIT;
    constexpr int CPP16 = CINS / 8;                 // 16B units per pixel (per ks chunk)
    constexpr int KC = CINS / 16;                   // k16 chunks per tap per ks
    constexpr int A_BYTES = SROWS * W * CINS * 2;
    constexpr int RES_BYTES = 64 * 132 * 4;
    constexpr int SM_BYTES = (A_BYTES > RES_BYTES ? A_BYTES : RES_BYTES);

    const uint16_t* __restrict__ Xin;
    const uint16_t* __restrict__ BT;
    uint16_t* __restrict__ Xout = nullptr;
    float*    __restrict__ Fout = nullptr;
    if constexpr (L == 2)      { Xin = g_X2; BT = g_B2; Xout = g_X3; }
    else if constexpr (L == 3) { Xin = g_X3; BT = g_B3; Xout = g_X4; }
    else if constexpr (L == 4) { Xin = g_X4; BT = g_B4; Xout = g_X5; }
    else if constexpr (L == 5) { Xin = g_X5; BT = g_B5; Xout = g_X6; }
    else                       { Xin = g_X6; BT = g_B6; Fout = g_H6; }

    __shared__ __align__(16) uint8_t smem[SM_BYTES + 16];
    float* sR = reinterpret_cast<float*>(smem);

    const int tid  = threadIdx.x;
    const int lane = tid & 31, warp = tid >> 5;
    const int wm = warp >> 2, wn = warp & 3;
    const int group = lane >> 2, tig = lane & 3;
    const int q = lane >> 3, rr = lane & 7;
    const int h = q >> 1;                           // k16-half (16B unit) this lane feeds

    const int bx = blockIdx.x, ny = blockIdx.y;
    const int b = bx / TPI, tile = bx % TPI;
    const int iy0 = tile * MROWS;
    const int nybase = ny * 128;

    const uint32_t sbase = (uint32_t)__cvta_generic_to_shared(smem);
    const uint32_t zaddr = sbase + SM_BYTES;
    if (tid < 4) *reinterpret_cast<uint32_t*>(smem + SM_BYTES + tid * 4) = 0u;

    // per-lane A pixel (row-major within tile), per m-frag
    int ry[2], px[2];
    #pragma unroll
    for (int mi = 0; mi < 2; ++mi) {
        int p = wm * 32 + mi * 16 + (q & 1) * 8 + rr;
        ry[mi] = p / W; px[mi] = p - ry[mi] * W;
    }

    float acc[2][4][4];
    #pragma unroll
    for (int mi = 0; mi < 2; ++mi)
        #pragma unroll
        for (int nf = 0; nf < 4; ++nf)
            #pragma unroll
            for (int v = 0; v < 4; ++v) acc[mi][nf][v] = 0.f;

    for (int ks = 0; ks < KSPLIT; ++ks) {
        if (ks) __syncthreads();
        // ---- stage A rows iy0-1 .. iy0+MROWS of k-chunk ks, pixel-XOR swizzled ----
        {
            constexpr int NV = SROWS * W * CPP16;
            for (int i = tid; i < NV; i += 256) {
                int sp = i / CPP16, c16 = i - sp * CPP16;
                int gy = iy0 - 1 + sp / W, gx = sp % W;
                uint4 v = make_uint4(0, 0, 0, 0);
                if ((unsigned)gy < (unsigned)H)
                    v = *reinterpret_cast<const uint4*>(
                        Xin + (((size_t)b * H + gy) * W + gx) * CIN + ks * CINS + c16 * 8);
                int d16 = sp * CPP16 + (c16 ^ (sp & 7));
                *reinterpret_cast<uint4*>(smem + d16 * 16) = v;
            }
        }
        __syncthreads();

        for (int tap = 0; tap < 9; ++tap) {
            const int ky = tap / 3, kx = tap % 3;
            uint32_t abase[2], ax7[2]; bool av[2];
            #pragma unroll
            for (int mi = 0; mi < 2; ++mi) {
                int sx = px[mi] + kx - 1;
                av[mi] = ((unsigned)sx < (unsigned)W);     // row halo staged as zeros
                int sp = (ry[mi] + ky) * W + sx;
                abase[mi] = sbase + (uint32_t)(sp * CPP16 * 16);
                ax7[mi]   = (uint32_t)(sp & 7);
            }
            const uint2* bv[4];
            #pragma unroll
            for (int nf = 0; nf < 4; ++nf) {
                int n = nybase + wn * 32 + nf * 8 + group;
                bv[nf] = reinterpret_cast<const uint2*>(
                    BT + (size_t)(tap * COUT + n) * CIN + ks * CINS + tig * 4);
            }
            #pragma unroll 2
            for (int kc = 0; kc < KC; ++kc) {
                uint32_t A[2][4];
                #pragma unroll
                for (int mi = 0; mi < 2; ++mi) {
                    uint32_t u = ((uint32_t)(kc * 2 + h)) ^ ax7[mi];
                    uint32_t ad = av[mi] ? (abase[mi] + (u << 4)) : zaddr;
                    asm volatile(
                        "ldmatrix.sync.aligned.m8n8.x4.shared.b16 {%0,%1,%2,%3}, [%4];"
                        : "=r"(A[mi][0]), "=r"(A[mi][1]), "=r"(A[mi][2]), "=r"(A[mi][3])
                        : "r"(ad));
                }
                #pragma unroll
                for (int nf = 0; nf < 4; ++nf) {
                    uint2 bw = bv[nf][kc * 4];
                    #pragma unroll
                    for (int mi = 0; mi < 2; ++mi) {
                        asm volatile(
                            "mma.sync.aligned.m16n8k16.row.col.f32.bf16.bf16.f32 "
                            "{%0,%1,%2,%3}, {%4,%5,%6,%7}, {%8,%9}, {%0,%1,%2,%3};"
                            : "+f"(acc[mi][nf][0]), "+f"(acc[mi][nf][1]),
                              "+f"(acc[mi][nf][2]), "+f"(acc[mi][nf][3])
                            : "r"(A[mi][0]), "r"(A[mi][1]), "r"(A[mi][2]), "r"(A[mi][3]),
                              "r"(bw.x), "r"(bw.y));
                    }
                }
            }
        }
    }
    __syncthreads();   // A no longer needed; reuse smem for results

    // spill accumulators: sR[pixel][n], pitch 132
    #pragma unroll
    for (int mi = 0; mi < 2; ++mi) {
        int r0 = wm * 32 + mi * 16 + group;
        #pragma unroll
        for (int nf = 0; nf < 4; ++nf) {
            int col = wn * 32 + nf * 8 + tig * 2;
            *reinterpret_cast<float2*>(&sR[r0 * 132 + col]) =
                make_float2(acc[mi][nf][0], acc[mi][nf][1]);
            *reinterpret_cast<float2*>(&sR[(r0 + 8) * 132 + col]) =
                make_float2(acc[mi][nf][2], acc[mi][nf][3]);
        }
    }
    __syncthreads();

    // ---- epilogue: relu (+pool) + bn + sign/float store ----
    if constexpr (POOL) {
        // 16 out px x 128 n; 16 threads per px, 8 n each
        int po = tid >> 4;
        int n0 = (tid & 15) * 8;
        int yo_l = po / (W / 2), xo_l = po % (W / 2);
        int p00 = (2 * yo_l) * W + 2 * xo_l;
        float fv[8];
        #pragma unroll
        for (int j = 0; j < 8; ++j) {
            int n = n0 + j;
            float m = fmaxf(fmaxf(sR[p00 * 132 + n],       sR[(p00 + 1) * 132 + n]),
                            fmaxf(sR[(p00 + W) * 132 + n], sR[(p00 + W + 1) * 132 + n]));
            m = fmaxf(m, 0.f);
            int ng = nybase + n;
            fv[j] = __fadd_rn(__fmul_rn(m, scale[ng]), bias[ng]);
        }
        int yo = iy0 / 2 + yo_l;
        size_t obase = (((size_t)b * (H / 2) + yo) * (W / 2) + xo_l) * COUT + nybase + n0;
        if constexpr (FOUT) {
            *reinterpret_cast<float4*>(Fout + obase)     = make_float4(fv[0], fv[1], fv[2], fv[3]);
            *reinterpret_cast<float4*>(Fout + obase + 4) = make_float4(fv[4], fv[5], fv[6], fv[7]);
        } else {
            uint32_t wds[4];
            #pragma unroll
            for (int qq = 0; qq < 4; ++qq)
                wds[qq] = ((fv[2*qq]   > 0.f) ? 0x3F80u : 0xBF80u) |
                         (((fv[2*qq+1] > 0.f) ? 0x3F80u : 0xBF80u) << 16);
            *reinterpret_cast<uint4*>(Xout + obase) = make_uint4(wds[0], wds[1], wds[2], wds[3]);
        }
    } else {
        // 64 px x 128 n; 4 iterations of 256 thr x 8 n
        #pragma unroll
        for (int it = 0; it < 4; ++it) {
            int t = it * 256 + tid;
            int lp = t >> 4;
            int n0 = (t & 15) * 8;
            int y = iy0 + lp / W, x = lp % W;
            float fv[8];
            #pragma unroll
            for (int j = 0; j < 8; ++j) {
                int n = n0 + j;
                float v = fmaxf(sR[lp * 132 + n], 0.f);
                int ng = nybase + n;
                fv[j] = __fadd_rn(__fmul_rn(v, scale[ng]), bias[ng]);
            }
            uint32_t wds[4];
            #pragma unroll
            for (int qq = 0; qq < 4; ++qq)
                wds[qq] = ((fv[2*qq]   > 0.f) ? 0x3F80u : 0xBF80u) |
                         (((fv[2*qq+1] > 0.f) ? 0x3F80u : 0xBF80u) << 16);
            size_t obase = (((size_t)b * H + y) * W + x) * COUT + nybase + n0;
            *reinterpret_cast<uint4*>(Xout + obase) = make_uint4(wds[0], wds[1], wds[2], wds[3]);
        }
    }
}

// ---------------- dense (512->10) + softmax, one warp per pixel ----------------
__global__ __launch_bounds__(128) void dense_kernel(
    const float* __restrict__ dw, const float* __restrict__ db, float* __restrict__ out)
{
    __shared__ float sdw[512 * 10];
    const int tid = threadIdx.x;
    for (int i = tid; i < 5120; i += 128) {
        int c = i / 10, d = i % 10;
        sdw[d * 512 + c] = dw[i];
    }
    __syncthreads();
    const int warp = tid >> 5, lane = tid & 31;
    const int p = blockIdx.x * 4 + warp;
    float lg[10];
    #pragma unroll
    for (int d = 0; d < 10; ++d) lg[d] = 0.f;
    for (int c = lane; c < 512; c += 32) {
        float hh = g_H6[(size_t)p * 512 + c];
        #pragma unroll
        for (int d = 0; d < 10; ++d) lg[d] += hh * sdw[d * 512 + c];
    }
    #pragma unroll
    for (int d = 0; d < 10; ++d)
        for (int off = 16; off; off >>= 1)
            lg[d] += __shfl_xor_sync(FULLMASK, lg[d], off);
    if (lane == 0) {
        float l[10], mx = -1e30f;
        #pragma unroll
        for (int d = 0; d < 10; ++d) { l[d] = lg[d] + db[d]; mx = fmaxf(mx, l[d]); }
        float e[10], ssum = 0.f;
        #pragma unroll
        for (int d = 0; d < 10; ++d) { e[d] = expf(l[d] - mx); ssum += e[d]; }
        float inv = 1.f / ssum;
        #pragma unroll
        for (int d = 0; d < 10; ++d) out[(size_t)p * 10 + d] = e[d] * inv;
    }
}

// ---------------- launch ----------------
extern "C" void kernel_launch(void* const* d_in, const int* in_sizes, int n_in,
                              void* d_out, int out_size)
{
    const float* P[22];
    for (int i = 0; i < 22 && i < n_in; ++i) P[i] = (const float*)d_in[i];

    const float *x, *w1, *b1, *w2, *w3, *w4, *w5, *w6;
    const float *bn1s, *bn1b, *bn2s, *bn2b, *bn3s, *bn3b, *bn4s, *bn4b, *bn5s, *bn5b, *bn6s, *bn6b;
    const float *dw, *db;

    if (in_sizes[3] == 147456) {
        // setup_inputs dict order
        x = P[0];  w1 = P[1]; b1 = P[2];
        w2 = P[3]; w3 = P[4]; w4 = P[5]; w5 = P[6]; w6 = P[7];
        bn1s = P[8];  bn1b = P[9];  bn2s = P[10]; bn2b = P[11];
        bn3s = P[12]; bn3b = P[13]; bn4s = P[14]; bn4b = P[15];
        bn5s = P[16]; bn5b = P[17]; bn6s = P[18]; bn6b = P[19];
        dw = P[20]; db = P[21];
    } else {
        // reference() signature order
        x = P[0];  w1 = P[1]; b1 = P[2]; bn1s = P[3]; bn1b = P[4];
        w2 = P[5];  bn2s = P[6];  bn2b = P[7];
        w3 = P[8];  bn3s = P[9];  bn3b = P[10];
        w4 = P[11]; bn4s = P[12]; bn4b = P[13];
        w5 = P[14]; bn5s = P[15]; bn5b = P[16];
        w6 = P[17]; bn6s = P[18]; bn6b = P[19];
        dw = P[20]; db = P[21];
    }

    pack_all<<<(285696 + 255) / 256, 256>>>(w2, w3, w4, w5, w6);

    conv1_kernel<<<dim3(32, 128), 128>>>(x, w1, b1, bn1s, bn1b);

    tcconv<2><<<dim3(128 * 16, 1), 256>>>(bn2s, bn2b);
    tcconv<3><<<dim3(128 * 4, 2),  256>>>(bn3s, bn3b);
    tcconv<4><<<dim3(128 * 4, 2),  256>>>(bn4s, bn4b);
    tcconv<5><<<dim3(128, 4),      256>>>(bn5s, bn5b);
    tcconv<6><<<dim3(128, 4),      256>>>(bn6s, bn6b);

    dense_kernel<<<512, 128>>>(dw, db, (float*)d_out);
}

// round 12
// speedup vs baseline: 4.0369x; 1.9761x over previous
#include <cuda_runtime.h>
#include <stdint.h>

#define FULLMASK 0xffffffffu

// ---------------- scratch (device globals; referenced ONLY in device code) ----------------
// activations bf16 (+1/-1) raw uint16, NHWC
__device__ __align__(256) uint16_t g_X2[128*32*32*128];
__device__ __align__(256) uint16_t g_X3[128*16*16*128];
__device__ __align__(256) uint16_t g_X4[128*16*16*256];
__device__ __align__(256) uint16_t g_X5[128*8*8*256];
__device__ __align__(256) uint16_t g_X6[128*8*8*512];
__device__ __align__(256) float    g_H6[128*4*4*512];
// weights bf16 +-1, FRAGMENT-MAJOR: 8B block for (tap, nblk, kcf, nf, lane) at
// linear block idx (((tap*(COUT/32)+nblk)*(CIN/16)+kcf)*4+nf)*32+lane, so a
// warp's B fragment load is one contiguous 256B LDG.64.
__device__ __align__(256) uint16_t g_B2[9*128*128];
__device__ __align__(256) uint16_t g_B3[9*256*128];
__device__ __align__(256) uint16_t g_B4[9*256*256];
__device__ __align__(256) uint16_t g_B5[9*512*256];
__device__ __align__(256) uint16_t g_B6[9*512*512];

// ---------------- weight sign-packing to bf16 +-1 (fragment-major) ----------------
// Per-thread READ pattern identical to the validated R8 pack; only the STORE
// location changes (contiguous 32B per thread in the new layout).
__device__ __forceinline__ void pack16(const float* __restrict__ w, uint16_t* __restrict__ bt,
                                       int CIN, int COUT, int o)
{
    int cout = o % COUT;
    int r    = o / COUT;
    int kcf  = r % (CIN / 16);
    int tap  = r / (CIN / 16);
    const float* base = w + ((size_t)(tap * CIN + kcf * 16)) * COUT + cout;
    uint32_t wd[8];
    #pragma unroll
    for (int qq = 0; qq < 8; ++qq) {
        int k0 = (qq & 1) * 8 + (qq >> 1) * 2;
        uint32_t lo = (base[(size_t)k0 * COUT]       > 0.f) ? 0x3F80u : 0xBF80u;
        uint32_t hi = (base[(size_t)(k0 + 1) * COUT] > 0.f) ? 0x3F80u : 0xBF80u;
        wd[qq] = lo | (hi << 16);
    }
    int nblk = cout >> 5;
    int nf   = (cout >> 3) & 3;
    int group = cout & 7;
    size_t blk8 = ((((size_t)tap * (COUT / 32) + nblk) * (CIN / 16) + kcf) * 4 + nf) * 32
                  + group * 4;     // tig 0..3 occupy 4 consecutive 8B slots
    uint4* dst = reinterpret_cast<uint4*>(bt + blk8 * 4);
    dst[0] = make_uint4(wd[0], wd[1], wd[2], wd[3]);
    dst[1] = make_uint4(wd[4], wd[5], wd[6], wd[7]);
}

__global__ void pack_all(const float* __restrict__ w2, const float* __restrict__ w3,
                         const float* __restrict__ w4, const float* __restrict__ w5,
                         const float* __restrict__ w6)
{
    int idx = blockIdx.x * blockDim.x + threadIdx.x;
    if      (idx <   9216) pack16(w2, g_B2, 128, 128, idx);
    else if (idx <  27648) pack16(w3, g_B3, 128, 256, idx - 9216);
    else if (idx <  64512) pack16(w4, g_B4, 256, 256, idx - 27648);
    else if (idx < 138240) pack16(w5, g_B5, 256, 512, idx - 64512);
    else if (idx < 285696) pack16(w6, g_B6, 512, 512, idx - 138240);
}

// ---------------- layer 1: float conv 3->128 + relu + b1 + bn1 -> bf16 sign ----------------
__global__ __launch_bounds__(128) void conv1_kernel(
    const float* __restrict__ x, const float* __restrict__ w1,
    const float* __restrict__ b1, const float* __restrict__ sc1,
    const float* __restrict__ bi1)
{
    __shared__ float xs[3 * 34 * 3];
    const int tid = threadIdx.x;
    const int y = blockIdx.x, b = blockIdx.y;

    for (int i = tid; i < 3 * 34 * 3; i += 128) xs[i] = 0.f;
    __syncthreads();
    for (int j = 0; j < 3; ++j) {
        int gy = y + j - 1;
        if (gy < 0 || gy >= 32) continue;
        if (tid < 96) {
            int c = tid / 3, ci = tid % 3;
            xs[(j * 34 + c + 1) * 3 + ci] = x[((size_t)(b * 32 + gy) * 32 + c) * 3 + ci];
        }
    }
    __syncthreads();

    float wr[27];
    #pragma unroll
    for (int k = 0; k < 27; ++k) wr[k] = w1[k * 128 + tid];
    const float bv = b1[tid], scv = sc1[tid], biv = bi1[tid];

    for (int c = 0; c < 32; ++c) {
        float sum = 0.f;
        #pragma unroll
        for (int ky = 0; ky < 3; ++ky)
            #pragma unroll
            for (int kx = 0; kx < 3; ++kx)
                #pragma unroll
                for (int ci = 0; ci < 3; ++ci)
                    sum += xs[(ky * 34 + c + kx) * 3 + ci] * wr[(ky * 3 + kx) * 3 + ci];
        float h = fmaxf(sum + bv, 0.f);
        float f = __fadd_rn(__fmul_rn(h, scv), biv);
        g_X2[((size_t)(b * 32 + y) * 32 + c) * 128 + tid] = (f > 0.f) ? 0x3F80 : 0xBF80;
    }
}

// ---------------- layer params (CTA tile M=64 x N=128; warp tile m64 x n32) ----------------
template <int L> struct LP;
template <> struct LP<2> { static constexpr int H=32,W=32,CIN=128,COUT=128,KSPLIT=1; static constexpr bool POOL=true,  FOUT=false; };
template <> struct LP<3> { static constexpr int H=16,W=16,CIN=128,COUT=256,KSPLIT=1; static constexpr bool POOL=false, FOUT=false; };
template <> struct LP<4> { static constexpr int H=16,W=16,CIN=256,COUT=256,KSPLIT=2; static constexpr bool POOL=true,  FOUT=false; };
template <> struct LP<5> { static constexpr int H=8, W=8, CIN=256,COUT=512,KSPLIT=1; static constexpr bool POOL=false, FOUT=false; };
template <> struct LP<6> { static constexpr int H=8, W=8, CIN=512,COUT=512,KSPLIT=2; static constexpr bool POOL=true,  FOUT=true;  };

// ---------------- binary conv: bf16 HMMA implicit GEMM ----------------
// block 128 thr = 4 n-warps; warp tile m64 x n32 (4 mi x 4 nf), k16 bf16 mma.
template <int L>
__global__ __launch_bounds__(128) void tcconv(const float* __restrict__ scale,
                                              const float* __restrict__ bias)
{
    constexpr int H = LP<L>::H, W = LP<L>::W, CIN = LP<L>::CIN, COUT = LP<L>::COUT;
    constexpr int KSPLIT = LP<L>::KSPLIT;
    constexpr bool POOL = LP<L>::POOL, FOUT = LP<L>::FOUT;
    constexpr int MROWS = 64 / W;
    constexpr int TPI = H / MROWS;
    constexpr int SROWS = MROWS + 2;
    constexpr int CINS = CIN / KSPLIT;
    constexpr int CPP16 = CINS / 8;                 // 16B units per pixel (per ks chunk)
    constexpr int KC = CINS / 16;                   // k16 chunks per tap per ks
    constexpr int A_BYTES = SROWS * W * CINS * 2;
    constexpr int RES_BYTES = 64 * 132 * 4;
    constexpr int SM_BYTES = (A_BYTES > RES_BYTES ? A_BYTES : RES_BYTES);

    const uint16_t* __restrict__ Xin;
    const uint16_t* __restrict__ BT;
    uint16_t* __restrict__ Xout = nullptr;
    float*    __restrict__ Fout = nullptr;
    if constexpr (L == 2)      { Xin = g_X2; BT = g_B2; Xout = g_X3; }
    else if constexpr (L == 3) { Xin = g_X3; BT = g_B3; Xout = g_X4; }
    else if constexpr (L == 4) { Xin = g_X4; BT = g_B4; Xout = g_X5; }
    else if constexpr (L == 5) { Xin = g_X5; BT = g_B5; Xout = g_X6; }
    else                       { Xin = g_X6; BT = g_B6; Fout = g_H6; }

    __shared__ __align__(16) uint8_t smem[SM_BYTES + 16];
    float* sR = reinterpret_cast<float*>(smem);

    const int tid  = threadIdx.x;
    const int lane = tid & 31, wn = tid >> 5;       // 4 n-warps
    const int group = lane >> 2, tig = lane & 3;
    const int q = lane >> 3, rr = lane & 7;
    const int h = q >> 1;                           // k16-half (16B unit) this lane feeds

    const int bx = blockIdx.x, ny = blockIdx.y;
    const int b = bx / TPI, tile = bx % TPI;
    const int iy0 = tile * MROWS;
    const int nybase = ny * 128;
    const int nb = ny * 4 + wn;                     // global 32-cout block for this warp

    const uint32_t sbase = (uint32_t)__cvta_generic_to_shared(smem);
    const uint32_t zaddr = sbase + SM_BYTES;
    if (tid < 4) *reinterpret_cast<uint32_t*>(smem + SM_BYTES + tid * 4) = 0u;

    // per-lane A pixel per m-frag (4 frags -> m64)
    int ry[4], px[4];
    #pragma unroll
    for (int mi = 0; mi < 4; ++mi) {
        int p = mi * 16 + (q & 1) * 8 + rr;
        ry[mi] = p / W; px[mi] = p - ry[mi] * W;
    }

    float acc[4][4][4];
    #pragma unroll
    for (int mi = 0; mi < 4; ++mi)
        #pragma unroll
        for (int nf = 0; nf < 4; ++nf)
            #pragma unroll
            for (int v = 0; v < 4; ++v) acc[mi][nf][v] = 0.f;

    for (int ks = 0; ks < KSPLIT; ++ks) {
        if (ks) __syncthreads();
        // ---- stage A rows iy0-1 .. iy0+MROWS of k-chunk ks, pixel-XOR swizzled ----
        {
            constexpr int NV = SROWS * W * CPP16;
            for (int i = tid; i < NV; i += 128) {
                int sp = i / CPP16, c16 = i - sp * CPP16;
                int gy = iy0 - 1 + sp / W, gx = sp % W;
                uint4 v = make_uint4(0, 0, 0, 0);
                if ((unsigned)gy < (unsigned)H)
                    v = *reinterpret_cast<const uint4*>(
                        Xin + (((size_t)b * H + gy) * W + gx) * CIN + ks * CINS + c16 * 8);
                int d16 = sp * CPP16 + (c16 ^ (sp & 7));
                *reinterpret_cast<uint4*>(smem + d16 * 16) = v;
            }
        }
        __syncthreads();

        for (int tap = 0; tap < 9; ++tap) {
            const int ky = tap / 3, kx = tap % 3;
            uint32_t abase[4], ax7[4]; bool av[4];
            #pragma unroll
            for (int mi = 0; mi < 4; ++mi) {
                int sx = px[mi] + kx - 1;
                av[mi] = ((unsigned)sx < (unsigned)W);     // row halo staged as zeros
                int sp = (ry[mi] + ky) * W + sx;
                abase[mi] = sbase + (uint32_t)(sp * CPP16 * 16);
                ax7[mi]   = (uint32_t)(sp & 7);
            }
            // fragment-major B: warp's fragment row = 128 uint2 per kcf
            const uint2* Bw = reinterpret_cast<const uint2*>(BT)
                + (((size_t)tap * (COUT / 32) + nb) * (CIN / 16) + ks * KC) * 128 + lane;
            #pragma unroll 2
            for (int kc = 0; kc < KC; ++kc) {
                uint32_t A[4][4];
                #pragma unroll
                for (int mi = 0; mi < 4; ++mi) {
                    uint32_t u = ((uint32_t)(kc * 2 + h)) ^ ax7[mi];
                    uint32_t ad = av[mi] ? (abase[mi] + (u << 4)) : zaddr;
                    asm volatile(
                        "ldmatrix.sync.aligned.m8n8.x4.shared.b16 {%0,%1,%2,%3}, [%4];"
                        : "=r"(A[mi][0]), "=r"(A[mi][1]), "=r"(A[mi][2]), "=r"(A[mi][3])
                        : "r"(ad));
                }
                #pragma unroll
                for (int nf = 0; nf < 4; ++nf) {
                    uint2 bw = Bw[(kc * 4 + nf) * 32];
                    #pragma unroll
                    for (int mi = 0; mi < 4; ++mi) {
                        asm volatile(
                            "mma.sync.aligned.m16n8k16.row.col.f32.bf16.bf16.f32 "
                            "{%0,%1,%2,%3}, {%4,%5,%6,%7}, {%8,%9}, {%0,%1,%2,%3};"
                            : "+f"(acc[mi][nf][0]), "+f"(acc[mi][nf][1]),
                              "+f"(acc[mi][nf][2]), "+f"(acc[mi][nf][3])
                            : "r"(A[mi][0]), "r"(A[mi][1]), "r"(A[mi][2]), "r"(A[mi][3]),
                              "r"(bw.x), "r"(bw.y));
                    }
                }
            }
        }
    }
    __syncthreads();   // A no longer needed; reuse smem for results

    // spill accumulators: sR[pixel][n], pitch 132
    #pragma unroll
    for (int mi = 0; mi < 4; ++mi) {
        int r0 = mi * 16 + group;
        #pragma unroll
        for (int nf = 0; nf < 4; ++nf) {
            int col = wn * 32 + nf * 8 + tig * 2;
            *reinterpret_cast<float2*>(&sR[r0 * 132 + col]) =
                make_float2(acc[mi][nf][0], acc[mi][nf][1]);
            *reinterpret_cast<float2*>(&sR[(r0 + 8) * 132 + col]) =
                make_float2(acc[mi][nf][2], acc[mi][nf][3]);
        }
    }
    __syncthreads();

    // ---- epilogue: relu (+pool) + bn + sign/float store ----
    if constexpr (POOL) {
        // 16 out px x 128 n; 8 threads per px, 16 n each
        int po = tid >> 3;
        int n0 = (tid & 7) * 16;
        int yo_l = po / (W / 2), xo_l = po % (W / 2);
        int p00 = (2 * yo_l) * W + 2 * xo_l;
        float fv[16];
        #pragma unroll
        for (int j = 0; j < 16; ++j) {
            int n = n0 + j;
            float m = fmaxf(fmaxf(sR[p00 * 132 + n],       sR[(p00 + 1) * 132 + n]),
                            fmaxf(sR[(p00 + W) * 132 + n], sR[(p00 + W + 1) * 132 + n]));
            m = fmaxf(m, 0.f);
            int ng = nybase + n;
            fv[j] = __fadd_rn(__fmul_rn(m, scale[ng]), bias[ng]);
        }
        int yo = iy0 / 2 + yo_l;
        size_t obase = (((size_t)b * (H / 2) + yo) * (W / 2) + xo_l) * COUT + nybase + n0;
        if constexpr (FOUT) {
            #pragma unroll
            for (int qq = 0; qq < 4; ++qq)
                *reinterpret_cast<float4*>(Fout + obase + qq * 4) =
                    make_float4(fv[4*qq], fv[4*qq+1], fv[4*qq+2], fv[4*qq+3]);
        } else {
            uint32_t wds[8];
            #pragma unroll
            for (int qq = 0; qq < 8; ++qq)
                wds[qq] = ((fv[2*qq]   > 0.f) ? 0x3F80u : 0xBF80u) |
                         (((fv[2*qq+1] > 0.f) ? 0x3F80u : 0xBF80u) << 16);
            uint4* op = reinterpret_cast<uint4*>(Xout + obase);
            op[0] = make_uint4(wds[0], wds[1], wds[2], wds[3]);
            op[1] = make_uint4(wds[4], wds[5], wds[6], wds[7]);
        }
    } else {
        // 64 px x 128 n; 8 iterations of 128 thr x 8 n
        #pragma unroll
        for (int it = 0; it < 8; ++it) {
            int t = it * 128 + tid;
            int lp = t >> 4;
            int n0 = (t & 15) * 8;
            int y = iy0 + lp / W, x = lp % W;
            float fv[8];
            #pragma unroll
            for (int j = 0; j < 8; ++j) {
                int n = n0 + j;
                float v = fmaxf(sR[lp * 132 + n], 0.f);
                int ng = nybase + n;
                fv[j] = __fadd_rn(__fmul_rn(v, scale[ng]), bias[ng]);
            }
            uint32_t wds[4];
            #pragma unroll
            for (int qq = 0; qq < 4; ++qq)
                wds[qq] = ((fv[2*qq]   > 0.f) ? 0x3F80u : 0xBF80u) |
                         (((fv[2*qq+1] > 0.f) ? 0x3F80u : 0xBF80u) << 16);
            size_t obase = (((size_t)b * H + y) * W + x) * COUT + nybase + n0;
            *reinterpret_cast<uint4*>(Xout + obase) = make_uint4(wds[0], wds[1], wds[2], wds[3]);
        }
    }
}

// ---------------- dense (512->10) + softmax, one warp per pixel ----------------
__global__ __launch_bounds__(128) void dense_kernel(
    const float* __restrict__ dw, const float* __restrict__ db, float* __restrict__ out)
{
    __shared__ float sdw[512 * 10];
    const int tid = threadIdx.x;
    for (int i = tid; i < 5120; i += 128) {
        int c = i / 10, d = i % 10;
        sdw[d * 512 + c] = dw[i];
    }
    __syncthreads();
    const int warp = tid >> 5, lane = tid & 31;
    const int p = blockIdx.x * 4 + warp;
    float lg[10];
    #pragma unroll
    for (int d = 0; d < 10; ++d) lg[d] = 0.f;
    for (int c = lane; c < 512; c += 32) {
        float hh = g_H6[(size_t)p * 512 + c];
        #pragma unroll
        for (int d = 0; d < 10; ++d) lg[d] += hh * sdw[d * 512 + c];
    }
    #pragma unroll
    for (int d = 0; d < 10; ++d)
        for (int off = 16; off; off >>= 1)
            lg[d] += __shfl_xor_sync(FULLMASK, lg[d], off);
    if (lane == 0) {
        float l[10], mx = -1e30f;
        #pragma unroll
        for (int d = 0; d < 10; ++d) { l[d] = lg[d] + db[d]; mx = fmaxf(mx, l[d]); }
        float e[10], ssum = 0.f;
        #pragma unroll
        for (int d = 0; d < 10; ++d) { e[d] = expf(l[d] - mx); ssum += e[d]; }
        float inv = 1.f / ssum;
        #pragma unroll
        for (int d = 0; d < 10; ++d) out[(size_t)p * 10 + d] = e[d] * inv;
    }
}

// ---------------- launch ----------------
extern "C" void kernel_launch(void* const* d_in, const int* in_sizes, int n_in,
                              void* d_out, int out_size)
{
    const float* P[22];
    for (int i = 0; i < 22 && i < n_in; ++i) P[i] = (const float*)d_in[i];

    const float *x, *w1, *b1, *w2, *w3, *w4, *w5, *w6;
    const float *bn1s, *bn1b, *bn2s, *bn2b, *bn3s, *bn3b, *bn4s, *bn4b, *bn5s, *bn5b, *bn6s, *bn6b;
    const float *dw, *db;

    if (in_sizes[3] == 147456) {
        // setup_inputs dict order
        x = P[0];  w1 = P[1]; b1 = P[2];
        w2 = P[3]; w3 = P[4]; w4 = P[5]; w5 = P[6]; w6 = P[7];
        bn1s = P[8];  bn1b = P[9];  bn2s = P[10]; bn2b = P[11];
        bn3s = P[12]; bn3b = P[13]; bn4s = P[14]; bn4b = P[15];
        bn5s = P[16]; bn5b = P[17]; bn6s = P[18]; bn6b = P[19];
        dw = P[20]; db = P[21];
    } else {
        // reference() signature order
        x = P[0];  w1 = P[1]; b1 = P[2]; bn1s = P[3]; bn1b = P[4];
        w2 = P[5];  bn2s = P[6];  bn2b = P[7];
        w3 = P[8];  bn3s = P[9];  bn3b = P[10];
        w4 = P[11]; bn4s = P[12]; bn4b = P[13];
        w5 = P[14]; bn5s = P[15]; bn5b = P[16];
        w6 = P[17]; bn6s = P[18]; bn6b = P[19];
        dw = P[20]; db = P[21];
    }

    pack_all<<<(285696 + 255) / 256, 256>>>(w2, w3, w4, w5, w6);

    conv1_kernel<<<dim3(32, 128), 128>>>(x, w1, b1, bn1s, bn1b);

    tcconv<2><<<dim3(128 * 16, 1), 128>>>(bn2s, bn2b);
    tcconv<3><<<dim3(128 * 4, 2),  128>>>(bn3s, bn3b);
    tcconv<4><<<dim3(128 * 4, 2),  128>>>(bn4s, bn4b);
    tcconv<5><<<dim3(128, 4),      128>>>(bn5s, bn5b);
    tcconv<6><<<dim3(128, 4),      128>>>(bn6s, bn6b);

    dense_kernel<<<512, 128>>>(dw, db, (float*)d_out);
}